// round 2
// baseline (speedup 1.0000x reference)
#include <cuda_runtime.h>
#include <cuda_bf16.h>
#include <cstdint>

#define EDGES      2048
#define DIM        200
#define CH         50
#define KDIM       10000
#define NBLK       4
#define MROWS      8192
#define NNODES     40943
#define GSPLIT     25
#define GKC        400            // KDIM / GSPLIT
#define NSTEP      25             // GKC / 16
#define CPART_STRIDE (MROWS * DIM)

// ------------------------- static scratch (no allocs) -----------------------
__device__ __align__(16) float g_A[(size_t)NBLK * EDGES * KDIM];      // 327.7 MB
__device__ __align__(16) float g_sck[NBLK * KDIM];
__device__ __align__(16) float g_shk[NBLK * KDIM];
__device__ __align__(16) float g_Cpart[(size_t)GSPLIT * MROWS * DIM]; // 163.8 MB
__device__ __align__(16) float g_Y[MROWS * DIM];
__device__ __align__(16) float g_bn2s[NBLK * DIM];
__device__ __align__(16) float g_bn2h[NBLK * DIM];

// ------------------------------- helpers ------------------------------------
__device__ __forceinline__ void ffma2(unsigned long long& d,
                                      unsigned long long a, unsigned long long b) {
    asm("fma.rn.f32x2 %0, %1, %2, %3;" : "=l"(d) : "l"(a), "l"(b), "l"(d));
}
__device__ __forceinline__ unsigned long long dup2(float x) {
    unsigned long long r; unsigned int u = __float_as_uint(x);
    asm("mov.b64 %0, {%1, %1};" : "=l"(r) : "r"(u));
    return r;
}
__device__ __forceinline__ void unpack2(unsigned long long v, float& lo, float& hi) {
    unsigned int a, b;
    asm("mov.b64 {%0, %1}, %2;" : "=r"(a), "=r"(b) : "l"(v));
    lo = __uint_as_float(a); hi = __uint_as_float(b);
}
__device__ __forceinline__ float bn_relu(float a, float s, float h) {
    return fmaxf(fmaf(a, s, h), 0.0f);
}

// ------------------------------ K0: zero out --------------------------------
__global__ void zero_kernel(float4* __restrict__ out) {
    const size_t total  = (size_t)EDGES * NNODES / 4;
    const size_t stride = (size_t)gridDim.x * blockDim.x;
    for (size_t i = (size_t)blockIdx.x * blockDim.x + threadIdx.x; i < total; i += stride)
        out[i] = make_float4(0.f, 0.f, 0.f, 0.f);
}

// --------------------------- K1: conv1d (raw) -------------------------------
__global__ void conv_kernel(const float* __restrict__ pre_emb, const float* __restrict__ r_emb,
                            const float* __restrict__ W2, const float* __restrict__ b2,
                            const float* __restrict__ W3, const float* __restrict__ b3,
                            const float* __restrict__ W4, const float* __restrict__ b4,
                            const int* __restrict__ src_ids, const int* __restrict__ edge_type,
                            const int* __restrict__ p1, const int* __restrict__ p2,
                            const int* __restrict__ p3) {
    const int e   = blockIdx.x;
    const int b   = blockIdx.y;
    const int tid = threadIdx.x;

    __shared__ float xs[4][204];      // [ch][0]=halo, [1..200]=data, [201]=halo
    __shared__ float ws[CH * 4 * 3];
    __shared__ float bsm[CH];

    int Cin; const float* W; const float* bias;
    int rel0 = 0, rel1 = 0, rel2 = 0;
    if (b == 0)      { Cin = 2; W = W2; bias = b2; rel0 = p1[e]; }
    else if (b == 1) { Cin = 3; W = W3; bias = b3; rel0 = p2[2*e]; rel1 = p2[2*e+1]; }
    else if (b == 2) { Cin = 4; W = W4; bias = b4; rel0 = p3[3*e]; rel1 = p3[3*e+1]; rel2 = p3[3*e+2]; }
    else             { Cin = 2; W = W2; bias = b2; rel0 = edge_type[e]; }

    const int sid = src_ids[e];
    const float* srcs[4];
    srcs[0] = pre_emb + (size_t)sid  * DIM;
    srcs[1] = r_emb   + (size_t)rel0 * DIM;
    srcs[2] = r_emb   + (size_t)rel1 * DIM;
    srcs[3] = r_emb   + (size_t)rel2 * DIM;

    for (int i = tid; i < Cin * DIM; i += 256) {
        int ch = i / DIM, d = i - ch * DIM;
        xs[ch][d + 1] = srcs[ch][d];
    }
    if (tid < 8) xs[tid >> 1][(tid & 1) ? 201 : 0] = 0.0f;
    for (int i = tid; i < CH * Cin * 3; i += 256) ws[i] = W[i];
    if (tid < CH) bsm[tid] = bias[tid];
    __syncthreads();

    float* outrow = g_A + (size_t)(b * EDGES + e) * KDIM;
    for (int idx = tid; idx < KDIM; idx += 256) {
        int c = idx / DIM, d = idx - c * DIM;
        float y = bsm[c];
        const float* wc = ws + c * Cin * 3;
        for (int i2 = 0; i2 < Cin; i2++)
            y += wc[i2*3+0] * xs[i2][d] + wc[i2*3+1] * xs[i2][d+1] + wc[i2*3+2] * xs[i2][d+2];
        outrow[idx] = y;
    }
}

// --------------------- K2: BN1 stats -> per-k scale/shift -------------------
__global__ void stats_kernel(const float* __restrict__ g1v, const float* __restrict__ be1v) {
    const int b   = blockIdx.x / CH;
    const int c   = blockIdx.x - b * CH;
    const int tid = threadIdx.x;

    __shared__ float ssum[256];
    __shared__ float ssq[256];

    float s[4] = {0.f,0.f,0.f,0.f}, q[4] = {0.f,0.f,0.f,0.f};
    if (tid < DIM) {
        const float* base = g_A + (size_t)b * EDGES * KDIM + c * DIM + tid;
        for (int e = 0; e < EDGES; e += 4) {
#pragma unroll
            for (int u = 0; u < 4; u++) {
                float v = base[(size_t)(e + u) * KDIM];
                s[u] += v; q[u] += v * v;
            }
        }
    }
    ssum[tid] = (s[0]+s[1]) + (s[2]+s[3]);
    ssq[tid]  = (q[0]+q[1]) + (q[2]+q[3]);
    __syncthreads();
    for (int off = 128; off > 0; off >>= 1) {
        if (tid < off) { ssum[tid] += ssum[tid+off]; ssq[tid] += ssq[tid+off]; }
        __syncthreads();
    }
    __shared__ float sc_sh[2];
    if (tid == 0) {
        const float inv = 1.0f / (float)(EDGES * DIM);
        float mu  = ssum[0] * inv;
        float var = ssq[0] * inv - mu * mu;
        float sc  = g1v[c] * rsqrtf(var + 1e-5f);
        sc_sh[0] = sc;
        sc_sh[1] = be1v[c] - mu * sc;
    }
    __syncthreads();
    if (tid < DIM) {
        g_sck[b * KDIM + c * DIM + tid] = sc_sh[0];
        g_shk[b * KDIM + c * DIM + tid] = sc_sh[1];
    }
}

// ----- K3: fused BN1+ReLU -> f32x2 GEMM, split-K=25, deterministic ----------
// C[m,n] = sum_k relu(sc[k]*A[m,k]+sh[k]) * fc_w[n,k]
// BM=128, BN=208 (200 valid), BK=16, 256 thr: TM=2 x TN=52 (26 f32x2 pairs)
__global__ __launch_bounds__(256, 1) void gemm_kernel(const float* __restrict__ Bw) {
    __shared__ __align__(16) float As[2][16][132];
    __shared__ __align__(16) float Bs[2][16][208];

    const int tid = threadIdx.x;
    const int mt  = blockIdx.x;           // 0..63
    const int ks  = blockIdx.y;           // 0..24
    const int m0  = mt * 128;
    const int blk = m0 >> 11;             // decode-block id 0..3
    const int k0  = ks * GKC;

    // A loader: 128x16 floats, 8/thread
    const int a_mr = tid >> 1;
    const int a_kq = (tid & 1) * 8;
    const float* aptr = g_A   + (size_t)(m0 + a_mr) * KDIM + k0 + a_kq;
    const float* scp  = g_sck + blk * KDIM + k0 + a_kq;
    const float* shp  = g_shk + blk * KDIM + k0 + a_kq;

    // B loader: 200 rows x 16 k as 800 float4 groups
    int gn[4], gk[4];
#pragma unroll
    for (int u = 0; u < 4; u++) { int g = tid + u * 256; gn[u] = g >> 2; gk[u] = (g & 3) * 4; }
    const int gcount = (tid < 32) ? 4 : 3;

    const int r  = tid & 63;              // row pair
    const int cg = tid >> 6;              // col group (52 cols)

    unsigned long long acc[2][26];
#pragma unroll
    for (int i = 0; i < 2; i++)
#pragma unroll
        for (int j = 0; j < 26; j++) acc[i][j] = 0ull;

    float4 av0, av1, sc0, sc1, sh0, sh1, bv[4];

    // prologue: tile 0
    av0 = *(const float4*)(aptr);     av1 = *(const float4*)(aptr + 4);
    sc0 = *(const float4*)(scp);      sc1 = *(const float4*)(scp + 4);
    sh0 = *(const float4*)(shp);      sh1 = *(const float4*)(shp + 4);
#pragma unroll
    for (int u = 0; u < 4; u++)
        if (u < gcount) bv[u] = *(const float4*)(Bw + (size_t)gn[u] * KDIM + k0 + gk[u]);

    As[0][a_kq+0][a_mr] = bn_relu(av0.x, sc0.x, sh0.x);
    As[0][a_kq+1][a_mr] = bn_relu(av0.y, sc0.y, sh0.y);
    As[0][a_kq+2][a_mr] = bn_relu(av0.z, sc0.z, sh0.z);
    As[0][a_kq+3][a_mr] = bn_relu(av0.w, sc0.w, sh0.w);
    As[0][a_kq+4][a_mr] = bn_relu(av1.x, sc1.x, sh1.x);
    As[0][a_kq+5][a_mr] = bn_relu(av1.y, sc1.y, sh1.y);
    As[0][a_kq+6][a_mr] = bn_relu(av1.z, sc1.z, sh1.z);
    As[0][a_kq+7][a_mr] = bn_relu(av1.w, sc1.w, sh1.w);
#pragma unroll
    for (int u = 0; u < 4; u++)
        if (u < gcount) {
            Bs[0][gk[u]+0][gn[u]] = bv[u].x;
            Bs[0][gk[u]+1][gn[u]] = bv[u].y;
            Bs[0][gk[u]+2][gn[u]] = bv[u].z;
            Bs[0][gk[u]+3][gn[u]] = bv[u].w;
        }

    int p = 0;
    for (int t = 0; t < NSTEP; t++) {
        __syncthreads();
        const bool more = (t + 1 < NSTEP);
        if (more) {
            const int koff = (t + 1) * 16;
            av0 = *(const float4*)(aptr + koff);   av1 = *(const float4*)(aptr + koff + 4);
            sc0 = *(const float4*)(scp + koff);    sc1 = *(const float4*)(scp + koff + 4);
            sh0 = *(const float4*)(shp + koff);    sh1 = *(const float4*)(shp + koff + 4);
#pragma unroll
            for (int u = 0; u < 4; u++)
                if (u < gcount) bv[u] = *(const float4*)(Bw + (size_t)gn[u] * KDIM + k0 + koff + gk[u]);
        }

#pragma unroll
        for (int kk = 0; kk < 16; kk++) {
            float2 a2 = *(const float2*)&As[p][kk][r * 2];
            unsigned long long pa0 = dup2(a2.x);
            unsigned long long pa1 = dup2(a2.y);
            const ulonglong2* brow = (const ulonglong2*)&Bs[p][kk][cg * 52];
#pragma unroll
            for (int j = 0; j < 13; j++) {
                ulonglong2 b2v = brow[j];
                ffma2(acc[0][2*j],   pa0, b2v.x);
                ffma2(acc[0][2*j+1], pa0, b2v.y);
                ffma2(acc[1][2*j],   pa1, b2v.x);
                ffma2(acc[1][2*j+1], pa1, b2v.y);
            }
        }

        if (more) {
            const int q = p ^ 1;
            As[q][a_kq+0][a_mr] = bn_relu(av0.x, sc0.x, sh0.x);
            As[q][a_kq+1][a_mr] = bn_relu(av0.y, sc0.y, sh0.y);
            As[q][a_kq+2][a_mr] = bn_relu(av0.z, sc0.z, sh0.z);
            As[q][a_kq+3][a_mr] = bn_relu(av0.w, sc0.w, sh0.w);
            As[q][a_kq+4][a_mr] = bn_relu(av1.x, sc1.x, sh1.x);
            As[q][a_kq+5][a_mr] = bn_relu(av1.y, sc1.y, sh1.y);
            As[q][a_kq+6][a_mr] = bn_relu(av1.z, sc1.z, sh1.z);
            As[q][a_kq+7][a_mr] = bn_relu(av1.w, sc1.w, sh1.w);
#pragma unroll
            for (int u = 0; u < 4; u++)
                if (u < gcount) {
                    Bs[q][gk[u]+0][gn[u]] = bv[u].x;
                    Bs[q][gk[u]+1][gn[u]] = bv[u].y;
                    Bs[q][gk[u]+2][gn[u]] = bv[u].z;
                    Bs[q][gk[u]+3][gn[u]] = bv[u].w;
                }
        }
        p ^= 1;
    }

    // epilogue -> split-K partials
    float* cp = g_Cpart + (size_t)ks * CPART_STRIDE + (size_t)m0 * DIM;
#pragma unroll
    for (int rr = 0; rr < 2; rr++) {
        const int m = r * 2 + rr;
#pragma unroll
        for (int j = 0; j < 26; j++) {
            float lo, hi;
            unpack2(acc[rr][j], lo, hi);
            const int n = cg * 52 + 2 * j;
            if (n < DIM)     cp[(size_t)m * DIM + n]     = lo;
            if (n + 1 < DIM) cp[(size_t)m * DIM + n + 1] = hi;
        }
    }
}

// ----------------- K4: split-K reduce (fixed order) + fc_b ------------------
__global__ void reduce_kernel(const float* __restrict__ fc_b) {
    const int i = blockIdx.x * 256 + threadIdx.x;   // 0..409599 float4 groups
    const float4* p = (const float4*)g_Cpart;
    const size_t stride4 = CPART_STRIDE / 4;
    float4 s = p[i];
#pragma unroll
    for (int u = 1; u < GSPLIT; u++) {
        float4 v = p[(size_t)u * stride4 + i];
        s.x += v.x; s.y += v.y; s.z += v.z; s.w += v.w;
    }
    const int n0 = (i * 4) % DIM;
    float4 bb = *(const float4*)(fc_b + n0);
    s.x += bb.x; s.y += bb.y; s.z += bb.z; s.w += bb.w;
    ((float4*)g_Y)[i] = s;
}

// --------------------------- K5: BN2 stats ----------------------------------
__global__ void bn2_kernel(const float* __restrict__ g2v, const float* __restrict__ be2v) {
    const int b   = blockIdx.x / DIM;
    const int n   = blockIdx.x - b * DIM;
    const int tid = threadIdx.x;

    __shared__ float ssum[256];
    __shared__ float ssq[256];

    float s = 0.f, q = 0.f;
    const float* base = g_Y + (size_t)(b * EDGES) * DIM + n;
#pragma unroll
    for (int u = 0; u < 8; u++) {
        float v = base[(size_t)(tid + u * 256) * DIM];
        s += v; q += v * v;
    }
    ssum[tid] = s; ssq[tid] = q;
    __syncthreads();
    for (int off = 128; off > 0; off >>= 1) {
        if (tid < off) { ssum[tid] += ssum[tid+off]; ssq[tid] += ssq[tid+off]; }
        __syncthreads();
    }
    if (tid == 0) {
        const float inv = 1.0f / (float)EDGES;
        float mu  = ssum[0] * inv;
        float var = ssq[0] * inv - mu * mu;
        float sc  = g2v[n] * rsqrtf(var + 1e-5f);
        g_bn2s[b * DIM + n] = sc;
        g_bn2h[b * DIM + n] = be2v[n] - mu * sc;
    }
}

// ----------------- K6: BN2+ReLU, cosine, scatter to output ------------------
__global__ void final_kernel(const int* __restrict__ o, float* __restrict__ out) {
    const int e    = blockIdx.x * 8 + (threadIdx.x >> 5);
    const int lane = threadIdx.x & 31;

    float dot[3] = {0.f,0.f,0.f}, nx[3] = {0.f,0.f,0.f}, nre = 0.f;
    for (int f = lane; f < DIM; f += 32) {
        float re = bn_relu(g_Y[(size_t)(3 * EDGES + e) * DIM + f],
                           g_bn2s[3 * DIM + f], g_bn2h[3 * DIM + f]);
        nre += re * re;
#pragma unroll
        for (int b = 0; b < 3; b++) {
            float xb = bn_relu(g_Y[(size_t)(b * EDGES + e) * DIM + f],
                               g_bn2s[b * DIM + f], g_bn2h[b * DIM + f]);
            dot[b] += xb * re;
            nx[b]  += xb * xb;
        }
    }
#pragma unroll
    for (int off = 16; off > 0; off >>= 1) {
        nre += __shfl_xor_sync(0xffffffffu, nre, off);
#pragma unroll
        for (int b = 0; b < 3; b++) {
            dot[b] += __shfl_xor_sync(0xffffffffu, dot[b], off);
            nx[b]  += __shfl_xor_sync(0xffffffffu, nx[b], off);
        }
    }
    if (lane == 0) {
        float nr = sqrtf(nre);
        float c = 0.f;
#pragma unroll
        for (int b = 0; b < 3; b++)
            c += dot[b] / fmaxf(sqrtf(nx[b]) * nr, 1e-8f);
        out[(size_t)e * NNODES + o[e]] = c;
    }
}

// ---------------------------------------------------------------------------
extern "C" void kernel_launch(void* const* d_in, const int* in_sizes, int n_in,
                              void* d_out, int out_size) {
    const float* pre_emb  = (const float*)d_in[0];
    const float* r_emb    = (const float*)d_in[1];
    const float* W2       = (const float*)d_in[2];
    const float* b2       = (const float*)d_in[3];
    const float* W3       = (const float*)d_in[4];
    const float* b3       = (const float*)d_in[5];
    const float* W4       = (const float*)d_in[6];
    const float* b4       = (const float*)d_in[7];
    const float* fc_w     = (const float*)d_in[8];
    const float* fc_b     = (const float*)d_in[9];
    const float* g1       = (const float*)d_in[10];
    const float* be1      = (const float*)d_in[11];
    const float* g2       = (const float*)d_in[12];
    const float* be2      = (const float*)d_in[13];
    const int*   src_ids  = (const int*)d_in[14];
    const int*   edge_type= (const int*)d_in[15];
    const int*   p1       = (const int*)d_in[16];
    const int*   p2       = (const int*)d_in[17];
    const int*   p3       = (const int*)d_in[18];
    const int*   o        = (const int*)d_in[19];
    float* out = (float*)d_out;

    zero_kernel<<<4096, 256>>>((float4*)out);
    conv_kernel<<<dim3(EDGES, NBLK), 256>>>(pre_emb, r_emb, W2, b2, W3, b3, W4, b4,
                                            src_ids, edge_type, p1, p2, p3);
    stats_kernel<<<NBLK * CH, 256>>>(g1, be1);
    gemm_kernel<<<dim3(MROWS / 128, GSPLIT), 256>>>(fc_w);
    reduce_kernel<<<(MROWS * DIM / 4) / 256, 256>>>(fc_b);
    bn2_kernel<<<NBLK * DIM, 256>>>(g2, be2);
    final_kernel<<<EDGES / 8, 256>>>(o, out);
}

// round 5
// speedup vs baseline: 1.0588x; 1.0588x over previous
#include <cuda_runtime.h>
#include <cuda_bf16.h>
#include <cstdint>

#define EDGES      2048
#define DIM        200
#define CH         50
#define KDIM       10000
#define NBLK       4
#define MROWS      8192
#define NNODES     40943
#define GSPLIT     25
#define GKC        400            // KDIM / GSPLIT
#define NSTEP      25             // GKC / 16
#define ECHUNKS    8
#define ECHSZ      256            // EDGES / ECHUNKS
#define CPART_STRIDE (MROWS * DIM)

// ------------------------- static scratch (no allocs) -----------------------
__device__ __align__(16) float g_A[(size_t)NBLK * EDGES * KDIM];      // 327.7 MB
__device__ __align__(16) float g_sck[NBLK * KDIM];
__device__ __align__(16) float g_shk[NBLK * KDIM];
__device__ __align__(16) float g_Cpart[(size_t)GSPLIT * MROWS * DIM]; // 163.8 MB
__device__ __align__(16) float g_Y[MROWS * DIM];
__device__ __align__(16) float g_bn2s[NBLK * DIM];
__device__ __align__(16) float g_bn2h[NBLK * DIM];
__device__ float g_ps[NBLK * CH * ECHUNKS];
__device__ float g_pq[NBLK * CH * ECHUNKS];

// ------------------------------- helpers ------------------------------------
__device__ __forceinline__ void ffma2(unsigned long long& d,
                                      unsigned long long a, unsigned long long b) {
    asm("fma.rn.f32x2 %0, %1, %2, %3;" : "=l"(d) : "l"(a), "l"(b), "l"(d));
}
__device__ __forceinline__ unsigned long long dup2(float x) {
    unsigned long long r; unsigned int u = __float_as_uint(x);
    asm("mov.b64 %0, {%1, %1};" : "=l"(r) : "r"(u));
    return r;
}
__device__ __forceinline__ float bn_relu(float a, float s, float h) {
    return fmaxf(fmaf(a, s, h), 0.0f);
}

// ------------------------------ K0: zero out --------------------------------
__global__ void zero_kernel(float4* __restrict__ out) {
    const size_t total  = (size_t)EDGES * NNODES / 4;
    const size_t stride = (size_t)gridDim.x * blockDim.x;
    for (size_t i = (size_t)blockIdx.x * blockDim.x + threadIdx.x; i < total; i += stride)
        out[i] = make_float4(0.f, 0.f, 0.f, 0.f);
}

// --------------------------- K1: conv1d (raw) -------------------------------
__global__ void conv_kernel(const float* __restrict__ pre_emb, const float* __restrict__ r_emb,
                            const float* __restrict__ W2, const float* __restrict__ b2,
                            const float* __restrict__ W3, const float* __restrict__ b3,
                            const float* __restrict__ W4, const float* __restrict__ b4,
                            const int* __restrict__ src_ids, const int* __restrict__ edge_type,
                            const int* __restrict__ p1, const int* __restrict__ p2,
                            const int* __restrict__ p3) {
    const int e   = blockIdx.x;
    const int b   = blockIdx.y;
    const int tid = threadIdx.x;

    __shared__ float xs[4][204];
    __shared__ float ws[CH * 4 * 3];
    __shared__ float bsm[CH];

    int Cin; const float* W; const float* bias;
    int rel0 = 0, rel1 = 0, rel2 = 0;
    if (b == 0)      { Cin = 2; W = W2; bias = b2; rel0 = p1[e]; }
    else if (b == 1) { Cin = 3; W = W3; bias = b3; rel0 = p2[2*e]; rel1 = p2[2*e+1]; }
    else if (b == 2) { Cin = 4; W = W4; bias = b4; rel0 = p3[3*e]; rel1 = p3[3*e+1]; rel2 = p3[3*e+2]; }
    else             { Cin = 2; W = W2; bias = b2; rel0 = edge_type[e]; }

    const int sid = src_ids[e];
    const float* srcs[4];
    srcs[0] = pre_emb + (size_t)sid  * DIM;
    srcs[1] = r_emb   + (size_t)rel0 * DIM;
    srcs[2] = r_emb   + (size_t)rel1 * DIM;
    srcs[3] = r_emb   + (size_t)rel2 * DIM;

    for (int i = tid; i < Cin * DIM; i += 256) {
        int ch = i / DIM, d = i - ch * DIM;
        xs[ch][d + 1] = srcs[ch][d];
    }
    if (tid < 8) xs[tid >> 1][(tid & 1) ? 201 : 0] = 0.0f;
    for (int i = tid; i < CH * Cin * 3; i += 256) ws[i] = W[i];
    if (tid < CH) bsm[tid] = bias[tid];
    __syncthreads();

    float* outrow = g_A + (size_t)(b * EDGES + e) * KDIM;
    for (int idx = tid; idx < KDIM; idx += 256) {
        int c = idx / DIM, d = idx - c * DIM;
        float y = bsm[c];
        const float* wc = ws + c * Cin * 3;
        for (int i2 = 0; i2 < Cin; i2++)
            y += wc[i2*3+0] * xs[i2][d] + wc[i2*3+1] * xs[i2][d+1] + wc[i2*3+2] * xs[i2][d+2];
        outrow[idx] = y;
    }
}

// ------------------- K2a: BN1 stats stage 1 (per e-chunk) -------------------
__global__ void stats1_kernel() {
    const int chunk = blockIdx.x & (ECHUNKS - 1);
    const int bc    = blockIdx.x >> 3;             // 0..199
    const int b     = bc / CH;
    const int c     = bc - b * CH;
    const int tid   = threadIdx.x;

    __shared__ float ssum[256];
    __shared__ float ssq[256];

    float s[8] = {0,0,0,0,0,0,0,0}, q[8] = {0,0,0,0,0,0,0,0};
    if (tid < DIM) {
        const float* base = g_A + (size_t)b * EDGES * KDIM
                          + (size_t)(chunk * ECHSZ) * KDIM + c * DIM + tid;
        for (int e = 0; e < ECHSZ; e += 8) {
#pragma unroll
            for (int u = 0; u < 8; u++) {
                float v = base[(size_t)(e + u) * KDIM];
                s[u] += v; q[u] += v * v;
            }
        }
    }
    float sa = ((s[0]+s[1])+(s[2]+s[3])) + ((s[4]+s[5])+(s[6]+s[7]));
    float qa = ((q[0]+q[1])+(q[2]+q[3])) + ((q[4]+q[5])+(q[6]+q[7]));
    ssum[tid] = sa; ssq[tid] = qa;
    __syncthreads();
    for (int off = 128; off > 0; off >>= 1) {
        if (tid < off) { ssum[tid] += ssum[tid+off]; ssq[tid] += ssq[tid+off]; }
        __syncthreads();
    }
    if (tid == 0) {
        g_ps[bc * ECHUNKS + chunk] = ssum[0];
        g_pq[bc * ECHUNKS + chunk] = ssq[0];
    }
}

// ------------- K2b: BN1 stats stage 2 -> expanded per-k scale/shift ---------
__global__ void stats2_kernel(const float* __restrict__ g1v, const float* __restrict__ be1v) {
    const int bc  = blockIdx.x;        // 0..199
    const int b   = bc / CH;
    const int c   = bc - b * CH;
    const int tid = threadIdx.x;

    __shared__ float sc_sh[2];
    if (tid == 0) {
        float s = 0.f, q = 0.f;
#pragma unroll
        for (int u = 0; u < ECHUNKS; u++) {
            s += g_ps[bc * ECHUNKS + u];
            q += g_pq[bc * ECHUNKS + u];
        }
        const float inv = 1.0f / (float)(EDGES * DIM);
        float mu  = s * inv;
        float var = q * inv - mu * mu;
        float sc  = g1v[c] * rsqrtf(var + 1e-5f);
        sc_sh[0] = sc;
        sc_sh[1] = be1v[c] - mu * sc;
    }
    __syncthreads();
    if (tid < DIM) {
        g_sck[b * KDIM + c * DIM + tid] = sc_sh[0];
        g_shk[b * KDIM + c * DIM + tid] = sc_sh[1];
    }
}

// ----- K3: fused BN1+ReLU -> f32x2 GEMM, split-K=25, deterministic ----------
// BM=128, BN=208(200 valid), BK=16, 512 thr: TM=2 x TN=26 (full 8x26 coverage)
__global__ __launch_bounds__(512, 1) void gemm_kernel(const float* __restrict__ Bw) {
    __shared__ __align__(16) float As[2][16][132];
    __shared__ __align__(16) float Bs[2][16][212];

    const int tid = threadIdx.x;
    const int mt  = blockIdx.x;           // 0..63
    const int ks  = blockIdx.y;           // 0..24
    const int m0  = mt * 128;
    const int blk = m0 >> 11;             // decode-block id 0..3
    const int k0  = ks * GKC;

    // A loader: 128x16 floats, one float4 per thread
    const int a_mr = tid >> 2;            // 0..127
    const int a_kq = (tid & 3) * 4;       // 0,4,8,12
    const float* aptr = g_A   + (size_t)(m0 + a_mr) * KDIM + k0 + a_kq;
    const float* scp  = g_sck + blk * KDIM + k0 + a_kq;
    const float* shp  = g_shk + blk * KDIM + k0 + a_kq;

    // B loader: 200 rows x 16 k = 800 float4 groups; <=2 per thread
    const int g0n = tid >> 2;             // 0..127
    const int g0k = (tid & 3) * 4;
    const int g1  = tid + 512;            // 512..1023, valid if < 800
    const int g1n = g1 >> 2;
    const int g1k = (g1 & 3) * 4;
    const bool has2 = (tid < 288);

    const int r  = tid & 63;              // row pair index (rows 2r, 2r+1)
    const int cg = tid >> 6;              // col group 0..7 (26 cols each)

    unsigned long long acc[2][13];
#pragma unroll
    for (int i = 0; i < 2; i++)
#pragma unroll
        for (int j = 0; j < 13; j++) acc[i][j] = 0ull;

    float4 av, sc, sh, bv0, bv1;

    // prologue: tile 0
    av = *(const float4*)(aptr);
    sc = *(const float4*)(scp);
    sh = *(const float4*)(shp);
    bv0 = *(const float4*)(Bw + (size_t)g0n * KDIM + k0 + g0k);
    if (has2) bv1 = *(const float4*)(Bw + (size_t)g1n * KDIM + k0 + g1k);

    As[0][a_kq+0][a_mr] = bn_relu(av.x, sc.x, sh.x);
    As[0][a_kq+1][a_mr] = bn_relu(av.y, sc.y, sh.y);
    As[0][a_kq+2][a_mr] = bn_relu(av.z, sc.z, sh.z);
    As[0][a_kq+3][a_mr] = bn_relu(av.w, sc.w, sh.w);
    Bs[0][g0k+0][g0n] = bv0.x;
    Bs[0][g0k+1][g0n] = bv0.y;
    Bs[0][g0k+2][g0n] = bv0.z;
    Bs[0][g0k+3][g0n] = bv0.w;
    if (has2) {
        Bs[0][g1k+0][g1n] = bv1.x;
        Bs[0][g1k+1][g1n] = bv1.y;
        Bs[0][g1k+2][g1n] = bv1.z;
        Bs[0][g1k+3][g1n] = bv1.w;
    }

    int p = 0;
    for (int t = 0; t < NSTEP; t++) {
        __syncthreads();
        const bool more = (t + 1 < NSTEP);
        if (more) {
            const int koff = (t + 1) * 16;
            av = *(const float4*)(aptr + koff);
            sc = *(const float4*)(scp + koff);
            sh = *(const float4*)(shp + koff);
            bv0 = *(const float4*)(Bw + (size_t)g0n * KDIM + k0 + koff + g0k);
            if (has2) bv1 = *(const float4*)(Bw + (size_t)g1n * KDIM + k0 + koff + g1k);
        }

#pragma unroll
        for (int kk = 0; kk < 16; kk++) {
            float2 a2 = *(const float2*)&As[p][kk][r * 2];
            unsigned long long pa0 = dup2(a2.x);
            unsigned long long pa1 = dup2(a2.y);
            const unsigned long long* brow = (const unsigned long long*)&Bs[p][kk][cg * 26];
#pragma unroll
            for (int j = 0; j < 13; j++) {
                unsigned long long bj = brow[j];
                ffma2(acc[0][j], pa0, bj);
                ffma2(acc[1][j], pa1, bj);
            }
        }

        if (more) {
            const int q = p ^ 1;
            As[q][a_kq+0][a_mr] = bn_relu(av.x, sc.x, sh.x);
            As[q][a_kq+1][a_mr] = bn_relu(av.y, sc.y, sh.y);
            As[q][a_kq+2][a_mr] = bn_relu(av.z, sc.z, sh.z);
            As[q][a_kq+3][a_mr] = bn_relu(av.w, sc.w, sh.w);
            Bs[q][g0k+0][g0n] = bv0.x;
            Bs[q][g0k+1][g0n] = bv0.y;
            Bs[q][g0k+2][g0n] = bv0.z;
            Bs[q][g0k+3][g0n] = bv0.w;
            if (has2) {
                Bs[q][g1k+0][g1n] = bv1.x;
                Bs[q][g1k+1][g1n] = bv1.y;
                Bs[q][g1k+2][g1n] = bv1.z;
                Bs[q][g1k+3][g1n] = bv1.w;
            }
        }
        p ^= 1;
    }

    // epilogue -> split-K partials (packed 8B stores; pairs never straddle 200)
    float* cp = g_Cpart + (size_t)ks * CPART_STRIDE + (size_t)m0 * DIM;
#pragma unroll
    for (int rr = 0; rr < 2; rr++) {
        const int m = r * 2 + rr;
        float* rowp = cp + (size_t)m * DIM;
#pragma unroll
        for (int j = 0; j < 13; j++) {
            const int n = cg * 26 + 2 * j;
            if (n < DIM)
                *(unsigned long long*)(rowp + n) = acc[rr][j];
        }
    }
}

// ----------------- K4: split-K reduce (fixed order) + fc_b ------------------
__global__ void reduce_kernel(const float* __restrict__ fc_b) {
    const int i = blockIdx.x * 256 + threadIdx.x;
    const float4* p = (const float4*)g_Cpart;
    const size_t stride4 = CPART_STRIDE / 4;
    float4 s = p[i];
#pragma unroll
    for (int u = 1; u < GSPLIT; u++) {
        float4 v = p[(size_t)u * stride4 + i];
        s.x += v.x; s.y += v.y; s.z += v.z; s.w += v.w;
    }
    const int n0 = (i * 4) % DIM;
    float4 bb = *(const float4*)(fc_b + n0);
    s.x += bb.x; s.y += bb.y; s.z += bb.z; s.w += bb.w;
    ((float4*)g_Y)[i] = s;
}

// --------------------------- K5: BN2 stats ----------------------------------
__global__ void bn2_kernel(const float* __restrict__ g2v, const float* __restrict__ be2v) {
    const int b   = blockIdx.x / DIM;
    const int n   = blockIdx.x - b * DIM;
    const int tid = threadIdx.x;

    __shared__ float ssum[256];
    __shared__ float ssq[256];

    float s = 0.f, q = 0.f;
    const float* base = g_Y + (size_t)(b * EDGES) * DIM + n;
#pragma unroll
    for (int u = 0; u < 8; u++) {
        float v = base[(size_t)(tid + u * 256) * DIM];
        s += v; q += v * v;
    }
    ssum[tid] = s; ssq[tid] = q;
    __syncthreads();
    for (int off = 128; off > 0; off >>= 1) {
        if (tid < off) { ssum[tid] += ssum[tid+off]; ssq[tid] += ssq[tid+off]; }
        __syncthreads();
    }
    if (tid == 0) {
        const float inv = 1.0f / (float)EDGES;
        float mu  = ssum[0] * inv;
        float var = ssq[0] * inv - mu * mu;
        float sc  = g2v[n] * rsqrtf(var + 1e-5f);
        g_bn2s[b * DIM + n] = sc;
        g_bn2h[b * DIM + n] = be2v[n] - mu * sc;
    }
}

// ----------------- K6: BN2+ReLU, cosine, scatter to output ------------------
__global__ void final_kernel(const int* __restrict__ o, float* __restrict__ out) {
    const int e    = blockIdx.x * 8 + (threadIdx.x >> 5);
    const int lane = threadIdx.x & 31;

    float dot[3] = {0.f,0.f,0.f}, nx[3] = {0.f,0.f,0.f}, nre = 0.f;
    for (int f = lane; f < DIM; f += 32) {
        float re = bn_relu(g_Y[(size_t)(3 * EDGES + e) * DIM + f],
                           g_bn2s[3 * DIM + f], g_bn2h[3 * DIM + f]);
        nre += re * re;
#pragma unroll
        for (int b = 0; b < 3; b++) {
            float xb = bn_relu(g_Y[(size_t)(b * EDGES + e) * DIM + f],
                               g_bn2s[b * DIM + f], g_bn2h[b * DIM + f]);
            dot[b] += xb * re;
            nx[b]  += xb * xb;
        }
    }
#pragma unroll
    for (int off = 16; off > 0; off >>= 1) {
        nre += __shfl_xor_sync(0xffffffffu, nre, off);
#pragma unroll
        for (int b = 0; b < 3; b++) {
            dot[b] += __shfl_xor_sync(0xffffffffu, dot[b], off);
            nx[b]  += __shfl_xor_sync(0xffffffffu, nx[b], off);
        }
    }
    if (lane == 0) {
        float nr = sqrtf(nre);
        float c = 0.f;
#pragma unroll
        for (int b = 0; b < 3; b++)
            c += dot[b] / fmaxf(sqrtf(nx[b]) * nr, 1e-8f);
        out[(size_t)e * NNODES + o[e]] = c;
    }
}

// ---------------------------------------------------------------------------
extern "C" void kernel_launch(void* const* d_in, const int* in_sizes, int n_in,
                              void* d_out, int out_size) {
    const float* pre_emb  = (const float*)d_in[0];
    const float* r_emb    = (const float*)d_in[1];
    const float* W2       = (const float*)d_in[2];
    const float* b2       = (const float*)d_in[3];
    const float* W3       = (const float*)d_in[4];
    const float* b3       = (const float*)d_in[5];
    const float* W4       = (const float*)d_in[6];
    const float* b4       = (const float*)d_in[7];
    const float* fc_w     = (const float*)d_in[8];
    const float* fc_b     = (const float*)d_in[9];
    const float* g1       = (const float*)d_in[10];
    const float* be1      = (const float*)d_in[11];
    const float* g2       = (const float*)d_in[12];
    const float* be2      = (const float*)d_in[13];
    const int*   src_ids  = (const int*)d_in[14];
    const int*   edge_type= (const int*)d_in[15];
    const int*   p1       = (const int*)d_in[16];
    const int*   p2       = (const int*)d_in[17];
    const int*   p3       = (const int*)d_in[18];
    const int*   o        = (const int*)d_in[19];
    float* out = (float*)d_out;

    zero_kernel<<<4096, 256>>>((float4*)out);
    conv_kernel<<<dim3(EDGES, NBLK), 256>>>(pre_emb, r_emb, W2, b2, W3, b3, W4, b4,
                                            src_ids, edge_type, p1, p2, p3);
    stats1_kernel<<<NBLK * CH * ECHUNKS, 256>>>();
    stats2_kernel<<<NBLK * CH, 256>>>(g1, be1);
    gemm_kernel<<<dim3(MROWS / 128, GSPLIT), 512>>>(fc_w);
    reduce_kernel<<<(MROWS * DIM / 4) / 256, 256>>>(fc_b);
    bn2_kernel<<<NBLK * DIM, 256>>>(g2, be2);
    final_kernel<<<EDGES / 8, 256>>>(o, out);
}